// round 12
// baseline (speedup 1.0000x reference)
#include <cuda_runtime.h>
#include <cuda_fp16.h>
#include <math.h>
#include <stdint.h>

#define B_ 8
#define H_ 512
#define L_ 4096
#define N_ 32
#define HN (H_ * N_)
#define O_ (2 * H_)

typedef unsigned long long ull;

// ---------------- scratch (__device__ globals) -----------------------------
__device__ float d_wr[HN], d_wi[HN], d_csr[HN], d_csi[HN];
__device__ __half d_g[(size_t)B_ * H_ * L_];      // natural layout [b][h][l]
__device__ __half d_Wf[(size_t)O_ * H_];          // single fp16 W plane

// ---------------------------------------------------------------------------
__device__ __forceinline__ uint32_t smem_u32(const void* p) {
    uint32_t a;
    asm("{ .reg .u64 t; cvta.to.shared.u64 t, %1; cvt.u32.u64 %0, t; }"
        : "=r"(a) : "l"(p));
    return a;
}

#define CP_ASYNC16(dst, src) \
    asm volatile("cp.async.cg.shared.global [%0], [%1], 16;" :: "r"(dst), "l"(src))
#define CP_COMMIT() asm volatile("cp.async.commit_group;" ::: "memory")
#define CP_WAIT1()  asm volatile("cp.async.wait_group 1;" ::: "memory")
#define CP_WAIT0()  asm volatile("cp.async.wait_group 0;" ::: "memory")

__device__ __forceinline__ void ldsm4(uint32_t* r, uint32_t addr) {
    asm volatile("ldmatrix.sync.aligned.m8n8.x4.shared.b16 {%0,%1,%2,%3}, [%4];"
                 : "=r"(r[0]), "=r"(r[1]), "=r"(r[2]), "=r"(r[3]) : "r"(addr));
}
__device__ __forceinline__ void ldsm4t(uint32_t* r, uint32_t addr) {
    asm volatile("ldmatrix.sync.aligned.m8n8.x4.trans.shared.b16 {%0,%1,%2,%3}, [%4];"
                 : "=r"(r[0]), "=r"(r[1]), "=r"(r[2]), "=r"(r[3]) : "r"(addr));
}

__device__ __forceinline__ void mma16816(float* d, const uint32_t* a,
                                         uint32_t b0, uint32_t b1) {
    asm volatile("mma.sync.aligned.m16n8k16.row.col.f32.f16.f16.f32 "
                 "{%0,%1,%2,%3}, {%4,%5,%6,%7}, {%8,%9}, {%0,%1,%2,%3};"
                 : "+f"(d[0]), "+f"(d[1]), "+f"(d[2]), "+f"(d[3])
                 : "r"(a[0]), "r"(a[1]), "r"(a[2]), "r"(a[3]), "r"(b0), "r"(b1));
}

// ---- packed fp32x2 (B300 FFMA2 path) ----
__device__ __forceinline__ ull pk2(float a, float b) {
    ull r;
    asm("mov.b64 %0, {%1, %2};" : "=l"(r) : "f"(a), "f"(b));
    return r;
}
__device__ __forceinline__ void upk2(float& a, float& b, ull v) {
    asm("mov.b64 {%0, %1}, %2;" : "=f"(a), "=f"(b) : "l"(v));
}
#define FMA2(d, a, b, c) \
    asm("fma.rn.f32x2 %0, %1, %2, %3;" : "=l"(d) : "l"(a), "l"(b), "l"(c))
#define MUL2(d, a, b) \
    asm("mul.rn.f32x2 %0, %1, %2;" : "=l"(d) : "l"(a), "l"(b))
#define ADD2(d, a, b) \
    asm("add.rn.f32x2 %0, %1, %2;" : "=l"(d) : "l"(a), "l"(b))

// ---------------------------------------------------------------------------
// Kernel 1: per (h,n) precompute  w = exp(dt*A),  2*Cs = 2*C*(w-1)/A
// ---------------------------------------------------------------------------
__global__ void prep_kernel(const float* __restrict__ log_dt,
                            const float* __restrict__ log_A_real,
                            const float* __restrict__ A_imag,
                            const float* __restrict__ C)
{
    int idx = blockIdx.x * blockDim.x + threadIdx.x;
    if (idx >= HN) return;
    int h = idx / N_;
    float dt = expf(log_dt[h]);
    float ar = -expf(log_A_real[idx]);
    float ai = A_imag[idx];
    float mag = expf(dt * ar);
    float wr = mag * cosf(dt * ai);
    float wi = mag * sinf(dt * ai);
    float den = ar * ar + ai * ai;
    float nr = wr - 1.0f, ni = wi;
    float qr = (nr * ar + ni * ai) / den;
    float qi = (ni * ar - nr * ai) / den;
    float Cr = C[2 * idx], Ci = C[2 * idx + 1];
    d_wr[idx]  = wr;
    d_wi[idx]  = wi;
    d_csr[idx] = 2.0f * (Cr * qr - Ci * qi);
    d_csi[idx] = 2.0f * (Cr * qi + Ci * qr);
}

// ---------------------------------------------------------------------------
// Kernel 1b: convert W to fp16
// ---------------------------------------------------------------------------
__global__ void wconv_kernel(const float* __restrict__ W)
{
    int idx = blockIdx.x * blockDim.x + threadIdx.x;
    if (idx >= O_ * H_) return;
    d_Wf[idx] = __float2half(W[idx]);
}

// ---------------------------------------------------------------------------
// Kernel 2: scan, z-form, packed f32x2, FOUR sequences per warp
// (two independent packed chains). Warp = (h, 4 batches), lane = mode.
// Per step: 1 LDS.128 (u quad) + 12 FMA2 + 1 STS.128.
// Per group: lane t reduces 32 modes x 4 seqs via 32 LDS.128 + ADD2 chains,
// D-skip, GELU x4, coalesced fp16 stores.
// smem/warp: red 32x(32x16B + 16B pad) = 16896B, us 512B -> 17408B.
// ---------------------------------------------------------------------------
#define SC_WARPS 4
#define SC_WBYTES 17408
#define SC_RSTR   528                   // row stride bytes: 33 x 16
#define SC_USOFF  16896
#define SCAN_SMEM (SC_WARPS * SC_WBYTES)   // 69632

__global__ __launch_bounds__(128) void scan_kernel(const float* __restrict__ u,
                                                   const float* __restrict__ D)
{
    extern __shared__ char sm2[];
    const int tid  = threadIdx.x;
    const int wid  = tid >> 5;
    const int lane = tid & 31;

    char* wbase = sm2 + wid * SC_WBYTES;
    const uint32_t red_a = smem_u32(wbase);
    const uint32_t us_a  = red_a + SC_USOFF;
    float4* us4 = (float4*)(wbase + SC_USOFF);

    const int gw  = blockIdx.x * SC_WARPS + wid;   // 0..1023
    const int b0  = (gw >> 9) * 4;                 // 0 or 4
    const int h   = gw & 511;

    const int idx = h * N_ + lane;
    const float wr  = d_wr[idx],  wi  = d_wi[idx];
    const float csr = d_csr[idx], csi = d_csi[idx];
    const float Dh  = D[h];

    const ull WR2  = pk2(wr, wr);
    const ull WI2  = pk2(wi, wi);
    const ull NWI2 = pk2(-wi, -wi);
    const ull CSR2 = pk2(csr, csr);
    const ull CSI2 = pk2(csi, csi);

    const float* up0 = u + ((size_t)(b0 + 0) * H_ + h) * L_;
    const float* up1 = u + ((size_t)(b0 + 1) * H_ + h) * L_;
    const float* up2 = u + ((size_t)(b0 + 2) * H_ + h) * L_;
    const float* up3 = u + ((size_t)(b0 + 3) * H_ + h) * L_;
    __half* gp0 = d_g + ((size_t)(b0 + 0) * H_ + h) * L_;
    __half* gp1 = d_g + ((size_t)(b0 + 1) * H_ + h) * L_;
    __half* gp2 = d_g + ((size_t)(b0 + 2) * H_ + h) * L_;
    __half* gp3 = d_g + ((size_t)(b0 + 3) * H_ + h) * L_;

    ull ZR01 = 0ull, ZI01 = 0ull, ZR23 = 0ull, ZI23 = 0ull;

    // 2-deep u prefetch, 4 sequences
    float u0a = up0[lane],      u1a = up1[lane];
    float u2a = up2[lane],      u3a = up3[lane];
    float u0b = up0[32 + lane], u1b = up1[32 + lane];
    float u2b = up2[32 + lane], u3b = up3[32 + lane];

    for (int l0 = 0; l0 < L_; l0 += 32) {
        us4[lane] = make_float4(u0a, u1a, u2a, u3a);
        u0a = u0b; u1a = u1b; u2a = u2b; u3a = u3b;
        if (l0 + 64 < L_) {
            u0b = up0[l0 + 64 + lane]; u1b = up1[l0 + 64 + lane];
            u2b = up2[l0 + 64 + lane]; u3b = up3[l0 + 64 + lane];
        }
        __syncwarp();

        #pragma unroll
        for (int t = 0; t < 32; t++) {
            ull UU01, UU23;
            asm volatile("ld.shared.v2.b64 {%0,%1}, [%2];"
                         : "=l"(UU01), "=l"(UU23) : "r"(us_a + t * 16));
            ull C0, C1, T0, T1;
            // chain A: seqs 0,1
            MUL2(C0, CSR2, UU01);
            MUL2(C1, CSI2, UU01);
            FMA2(T0, NWI2, ZI01, C0);
            FMA2(T1, WI2,  ZR01, C1);
            FMA2(ZR01, WR2, ZR01, T0);
            FMA2(ZI01, WR2, ZI01, T1);
            // chain B: seqs 2,3 (independent)
            ull C2, C3, T2, T3;
            MUL2(C2, CSR2, UU23);
            MUL2(C3, CSI2, UU23);
            FMA2(T2, NWI2, ZI23, C2);
            FMA2(T3, WI2,  ZR23, C3);
            FMA2(ZR23, WR2, ZR23, T2);
            FMA2(ZI23, WR2, ZI23, T3);
            asm volatile("st.shared.v2.b64 [%0], {%1,%2};"
                         :: "r"(red_a + (uint32_t)(t * SC_RSTR + lane * 16)),
                            "l"(ZR01), "l"(ZR23) : "memory");
        }
        __syncwarp();

        // reduce: lane t sums 32 modes for 4 seqs (2-deep ADD2 chains)
        {
            const uint32_t base = red_a + (uint32_t)(lane * SC_RSTR);
            ull A01a = 0ull, A23a = 0ull, A01b = 0ull, A23b = 0ull;
            #pragma unroll
            for (int n = 0; n < 32; n += 2) {
                ull v01, v23, w01, w23;
                asm volatile("ld.shared.v2.b64 {%0,%1}, [%2];"
                             : "=l"(v01), "=l"(v23) : "r"(base + n * 16));
                asm volatile("ld.shared.v2.b64 {%0,%1}, [%2];"
                             : "=l"(w01), "=l"(w23) : "r"(base + (n + 1) * 16));
                ADD2(A01a, A01a, v01);
                ADD2(A23a, A23a, v23);
                ADD2(A01b, A01b, w01);
                ADD2(A23b, A23b, w23);
            }
            ADD2(A01a, A01a, A01b);
            ADD2(A23a, A23a, A23b);
            float s0, s1, s2, s3;
            upk2(s0, s1, A01a);
            upk2(s2, s3, A23a);

            float4 uvt = us4[lane];          // u at t=lane for the 4 seqs
            float y0 = fmaf(Dh, uvt.x, s0);
            float y1 = fmaf(Dh, uvt.y, s1);
            float y2 = fmaf(Dh, uvt.z, s2);
            float y3 = fmaf(Dh, uvt.w, s3);
            const float k = 0.70710678118654752f;
            float g0 = 0.5f * y0 * (1.0f + erff(y0 * k));
            float g1 = 0.5f * y1 * (1.0f + erff(y1 * k));
            float g2 = 0.5f * y2 * (1.0f + erff(y2 * k));
            float g3 = 0.5f * y3 * (1.0f + erff(y3 * k));
            gp0[l0 + lane] = __float2half(g0);
            gp1[l0 + lane] = __float2half(g1);
            gp2[l0 + lane] = __float2half(g2);
            gp3[l0 + lane] = __float2half(g3);
        }
        __syncwarp();
    }
}

// ---------------------------------------------------------------------------
// Kernel 3: mma.sync fp16 GEMM + GLU, single pass (unchanged, proven 115us).
// CTA: M=128 (a + gate channel halves), N=128 l-cols, BK=32, 3-stage
// cp.async pipeline, 8 warps (4M x 2N), warp tile 32x64, 2 CTAs/SM.
// ---------------------------------------------------------------------------
#define BK 32
#define SSTR 80                              // A rows: 64B + 16B pad
#define SSTRB 272                            // B rows: 256B + 16B pad
#define TILE_A 10240                         // 128 * 80
#define TILE_B (BK * SSTRB)                  // 8704
#define OFF_B  TILE_A
#define STAGEB (TILE_A + TILE_B)             // 18944
#define NSTAGE (H_ / BK)                     // 16
#define SMEM_BYTES (3 * STAGEB)              // 56832
#define BSRC_STRIDE ((size_t)BK * L_ * 2)    // 262144 bytes per stage

__global__ __launch_bounds__(256, 2) void gemm_glu_mma(const float* __restrict__ bias,
                                                       float* __restrict__ out)
{
    extern __shared__ char smem[];
    const int tid  = threadIdx.x;
    const int wid  = tid >> 5;
    const int lane = tid & 31;

    const int b  = blockIdx.x >> 5;
    const int l0 = (blockIdx.x & 31) * 128;
    const int h0 = blockIdx.y * 64;

    const uint32_t sb = smem_u32(smem);
    const int wm = wid >> 1;
    const int wn = wid & 1;

    uint32_t aoff[2], boff[4];
    {
        int rr0 = wm * 32 + (lane & 15);
        int ka  = (lane >> 4) << 4;
        aoff[0] = (uint32_t)((rr0 +  0) * SSTR + ka);
        aoff[1] = (uint32_t)((rr0 + 16) * SSTR + ka);
        int rowb = (lane & 15) * SSTRB;
        int nbase = wn * 64 + ((lane >> 4) << 3);
        #pragma unroll
        for (int jb = 0; jb < 4; jb++)
            boff[jb] = (uint32_t)(OFF_B + rowb + (nbase + jb * 16) * 2);
    }

    const char* srcs[4];
    uint32_t    dsts[4];
    #pragma unroll
    for (int j = 0; j < 2; j++) {
        int id  = tid + 256 * j;
        int row = id >> 2;
        int seg = id & 3;
        int arow = h0 + row + ((row >= 64) ? 448 : 0);
        srcs[j] = (const char*)(d_Wf + (size_t)arow * H_) + seg * 16;
        dsts[j] = sb + row * SSTR + seg * 16;
    }
    #pragma unroll
    for (int j = 2; j < 4; j++) {
        int id  = tid + 256 * (j - 2);
        int row = id >> 4;
        int seg = id & 15;
        const __half* base = d_g + (size_t)b * H_ * L_;
        srcs[j] = (const char*)(base + (size_t)row * L_ + l0) + seg * 16;
        dsts[j] = sb + OFF_B + row * SSTRB + seg * 16;
    }

    #pragma unroll
    for (int j = 0; j < 4; j++) CP_ASYNC16(dsts[j], srcs[j]);
    CP_COMMIT();
    #pragma unroll
    for (int j = 0; j < 2; j++) CP_ASYNC16(dsts[j] + STAGEB, srcs[j] + 64);
    #pragma unroll
    for (int j = 2; j < 4; j++) CP_ASYNC16(dsts[j] + STAGEB, srcs[j] + BSRC_STRIDE);
    CP_COMMIT();

    float acc[2][8][4];
    #pragma unroll
    for (int mf = 0; mf < 2; mf++)
        #pragma unroll
        for (int nf = 0; nf < 8; nf++)
            #pragma unroll
            for (int e = 0; e < 4; e++) acc[mf][nf][e] = 0.0f;

    for (int s = 0; s < NSTAGE; s++) {
        if (s == NSTAGE - 1) { CP_WAIT0(); } else { CP_WAIT1(); }
        __syncthreads();

        const uint32_t st = sb + (uint32_t)(s % 3) * STAGEB;

        #pragma unroll
        for (int ks = 0; ks < 2; ks++) {
            const uint32_t ksoA = (uint32_t)(ks * 32);
            const uint32_t ksoB = (uint32_t)(ks * 16 * SSTRB);
            uint32_t aF[2][4], bF[4][4];
            #pragma unroll
            for (int mf = 0; mf < 2; mf++)
                ldsm4(aF[mf], st + aoff[mf] + ksoA);
            #pragma unroll
            for (int jb = 0; jb < 4; jb++)
                ldsm4t(bF[jb], st + boff[jb] + ksoB);
            #pragma unroll
            for (int mf = 0; mf < 2; mf++)
                #pragma unroll
                for (int jb = 0; jb < 4; jb++)
                    #pragma unroll
                    for (int hh = 0; hh < 2; hh++)
                        mma16816(acc[mf][jb * 2 + hh], aF[mf],
                                 bF[jb][2 * hh], bF[jb][2 * hh + 1]);
        }

        if (s + 2 < NSTAGE) {
            uint32_t dbo = (uint32_t)((s + 2) % 3) * STAGEB;
            #pragma unroll
            for (int j = 0; j < 2; j++)
                CP_ASYNC16(dsts[j] + dbo, srcs[j] + (size_t)(s + 2) * 64);
            #pragma unroll
            for (int j = 2; j < 4; j++)
                CP_ASYNC16(dsts[j] + dbo, srcs[j] + (size_t)(s + 2) * BSRC_STRIDE);
            CP_COMMIT();
        }
    }
    __syncthreads();

    // ---- epilogue: GLU ----
    float* sg = (float*)smem;               // [64][130] f32
    const int r0 = (lane >> 2);
    const int c0 = (lane & 3) * 2;

    if (wm >= 2) {
        #pragma unroll
        for (int mf = 0; mf < 2; mf++) {
            int row = wm * 32 + mf * 16 + r0;     // 64..127
            int grow = row - 64;
            float bg  = bias[H_ + h0 + grow];
            float bg2 = bias[H_ + h0 + grow + 8];
            #pragma unroll
            for (int nf = 0; nf < 8; nf++) {
                int col = wn * 64 + nf * 8 + c0;
                *(float2*)&sg[grow * 130 + col] =
                    make_float2(acc[mf][nf][0] + bg, acc[mf][nf][1] + bg);
                *(float2*)&sg[(grow + 8) * 130 + col] =
                    make_float2(acc[mf][nf][2] + bg2, acc[mf][nf][3] + bg2);
            }
        }
    }
    __syncthreads();
    if (wm < 2) {
        #pragma unroll
        for (int mf = 0; mf < 2; mf++) {
            int row = wm * 32 + mf * 16 + r0;     // 0..63
            int h  = h0 + row;
            float ba  = bias[h];
            float ba2 = bias[h + 8];
            float* ob  = out + ((size_t)b * H_ + h) * L_ + l0;
            float* ob2 = out + ((size_t)b * H_ + h + 8) * L_ + l0;
            #pragma unroll
            for (int nf = 0; nf < 8; nf++) {
                int col = wn * 64 + nf * 8 + c0;
                float2 g0 = *(const float2*)&sg[row * 130 + col];
                float2 g1 = *(const float2*)&sg[(row + 8) * 130 + col];
                float2 o0, o1;
                o0.x = (acc[mf][nf][0] + ba)  / (1.0f + expf(-g0.x));
                o0.y = (acc[mf][nf][1] + ba)  / (1.0f + expf(-g0.y));
                o1.x = (acc[mf][nf][2] + ba2) / (1.0f + expf(-g1.x));
                o1.y = (acc[mf][nf][3] + ba2) / (1.0f + expf(-g1.y));
                *(float2*)(ob  + col) = o0;
                *(float2*)(ob2 + col) = o1;
            }
        }
    }
}

// ---------------------------------------------------------------------------
extern "C" void kernel_launch(void* const* d_in, const int* in_sizes, int n_in,
                              void* d_out, int out_size)
{
    const float* u          = (const float*)d_in[0];
    const float* log_dt     = (const float*)d_in[1];
    const float* log_A_real = (const float*)d_in[2];
    const float* A_imag     = (const float*)d_in[3];
    const float* C          = (const float*)d_in[4];
    const float* D          = (const float*)d_in[5];
    const float* W_out      = (const float*)d_in[6];
    const float* b_out      = (const float*)d_in[7];
    float* out = (float*)d_out;

    static bool attr_set = false;
    if (!attr_set) {
        cudaFuncSetAttribute(gemm_glu_mma, cudaFuncAttributeMaxDynamicSharedMemorySize,
                             SMEM_BYTES);
        cudaFuncSetAttribute(scan_kernel, cudaFuncAttributeMaxDynamicSharedMemorySize,
                             SCAN_SMEM);
        attr_set = true;
    }

    prep_kernel<<<(HN + 127) / 128, 128>>>(log_dt, log_A_real, A_imag, C);
    wconv_kernel<<<(O_ * H_ + 255) / 256, 256>>>(W_out);

    // 1024 warps (4 sequences each), 4 warps/block
    scan_kernel<<<256, 128, SCAN_SMEM>>>(u, D);

    dim3 grid(B_ * (L_ / 128), H_ / 64);    // (256, 8)
    gemm_glu_mma<<<grid, 256, SMEM_BYTES>>>(b_out, out);
}

// round 13
// speedup vs baseline: 1.1394x; 1.1394x over previous
#include <cuda_runtime.h>
#include <cuda_fp16.h>
#include <math.h>
#include <stdint.h>

#define B_ 8
#define H_ 512
#define L_ 4096
#define N_ 32
#define HN (H_ * N_)
#define O_ (2 * H_)

typedef unsigned long long ull;

// ---------------- scratch (__device__ globals) -----------------------------
__device__ float d_wr[HN], d_wi[HN], d_csr[HN], d_csi[HN];
__device__ __half d_g[(size_t)B_ * H_ * L_];      // natural layout [b][h][l]
__device__ __half d_Wf[(size_t)O_ * H_];          // single fp16 W plane

// ---------------------------------------------------------------------------
__device__ __forceinline__ uint32_t smem_u32(const void* p) {
    uint32_t a;
    asm("{ .reg .u64 t; cvta.to.shared.u64 t, %1; cvt.u32.u64 %0, t; }"
        : "=r"(a) : "l"(p));
    return a;
}

#define CP_ASYNC16(dst, src) \
    asm volatile("cp.async.cg.shared.global [%0], [%1], 16;" :: "r"(dst), "l"(src))
#define CP_COMMIT() asm volatile("cp.async.commit_group;" ::: "memory")
#define CP_WAIT1()  asm volatile("cp.async.wait_group 1;" ::: "memory")
#define CP_WAIT0()  asm volatile("cp.async.wait_group 0;" ::: "memory")

__device__ __forceinline__ void ldsm4(uint32_t* r, uint32_t addr) {
    asm volatile("ldmatrix.sync.aligned.m8n8.x4.shared.b16 {%0,%1,%2,%3}, [%4];"
                 : "=r"(r[0]), "=r"(r[1]), "=r"(r[2]), "=r"(r[3]) : "r"(addr));
}
__device__ __forceinline__ void ldsm4t(uint32_t* r, uint32_t addr) {
    asm volatile("ldmatrix.sync.aligned.m8n8.x4.trans.shared.b16 {%0,%1,%2,%3}, [%4];"
                 : "=r"(r[0]), "=r"(r[1]), "=r"(r[2]), "=r"(r[3]) : "r"(addr));
}

__device__ __forceinline__ void mma16816(float* d, const uint32_t* a,
                                         uint32_t b0, uint32_t b1) {
    asm volatile("mma.sync.aligned.m16n8k16.row.col.f32.f16.f16.f32 "
                 "{%0,%1,%2,%3}, {%4,%5,%6,%7}, {%8,%9}, {%0,%1,%2,%3};"
                 : "+f"(d[0]), "+f"(d[1]), "+f"(d[2]), "+f"(d[3])
                 : "r"(a[0]), "r"(a[1]), "r"(a[2]), "r"(a[3]), "r"(b0), "r"(b1));
}

// ---- packed fp32x2 (B300 FFMA2 path) ----
__device__ __forceinline__ ull pk2(float a, float b) {
    ull r;
    asm("mov.b64 %0, {%1, %2};" : "=l"(r) : "f"(a), "f"(b));
    return r;
}
__device__ __forceinline__ void upk2(float& a, float& b, ull v) {
    asm("mov.b64 {%0, %1}, %2;" : "=f"(a), "=f"(b) : "l"(v));
}
#define FMA2(d, a, b, c) \
    asm("fma.rn.f32x2 %0, %1, %2, %3;" : "=l"(d) : "l"(a), "l"(b), "l"(c))
#define MUL2(d, a, b) \
    asm("mul.rn.f32x2 %0, %1, %2;" : "=l"(d) : "l"(a), "l"(b))

// ---------------------------------------------------------------------------
// Kernel 1: per (h,n) precompute  w = exp(dt*A),  2*Cs = 2*C*(w-1)/A
// ---------------------------------------------------------------------------
__global__ void prep_kernel(const float* __restrict__ log_dt,
                            const float* __restrict__ log_A_real,
                            const float* __restrict__ A_imag,
                            const float* __restrict__ C)
{
    int idx = blockIdx.x * blockDim.x + threadIdx.x;
    if (idx >= HN) return;
    int h = idx / N_;
    float dt = expf(log_dt[h]);
    float ar = -expf(log_A_real[idx]);
    float ai = A_imag[idx];
    float mag = expf(dt * ar);
    float wr = mag * cosf(dt * ai);
    float wi = mag * sinf(dt * ai);
    float den = ar * ar + ai * ai;
    float nr = wr - 1.0f, ni = wi;
    float qr = (nr * ar + ni * ai) / den;
    float qi = (ni * ar - nr * ai) / den;
    float Cr = C[2 * idx], Ci = C[2 * idx + 1];
    d_wr[idx]  = wr;
    d_wi[idx]  = wi;
    d_csr[idx] = 2.0f * (Cr * qr - Ci * qi);
    d_csi[idx] = 2.0f * (Cr * qi + Ci * qr);
}

// ---------------------------------------------------------------------------
// Kernel 1b: convert W to fp16
// ---------------------------------------------------------------------------
__global__ void wconv_kernel(const float* __restrict__ W)
{
    int idx = blockIdx.x * blockDim.x + threadIdx.x;
    if (idx >= O_ * H_) return;
    d_Wf[idx] = __float2half(W[idx]);
}

// ---------------------------------------------------------------------------
// Kernel 2: scan, z-form, f32x2 packed over MODE PAIRS, 2 sequences/warp.
// lane = (seq = lane/16, modes 2m,2m+1 with m = lane&15).
// Per step: 1 LDS.32 (u bcast) + pack + 6 f32x2 + 1 FADD (halves) + 1 STS.32.
// Per group: lane t reads its 128B row (8 LDS.128, conflict-free @144B
// stride), sums 16+16, D-skip, GELU, coalesced fp16 stores.
// ---------------------------------------------------------------------------
#define SC_RSTR 144                      // red row stride bytes (128 + 16 pad)
#define SC_REDB (32 * SC_RSTR)           // 4608
#define SC_WB   (SC_REDB + 256)          // + us staging = 4864 B per warp

__global__ __launch_bounds__(256) void scan_kernel(const float* __restrict__ u,
                                                   const float* __restrict__ D)
{
    __shared__ __align__(16) char sm2[8 * SC_WB];   // 38912 B

    const int tid  = threadIdx.x;
    const int wid  = tid >> 5;
    const int lane = tid & 31;

    char* wbase = sm2 + wid * SC_WB;
    const uint32_t red_a = smem_u32(wbase);
    const uint32_t us_a  = red_a + SC_REDB;
    float2* us2 = (float2*)(wbase + SC_REDB);

    const int gw = blockIdx.x * 8 + wid;     // 0..2047
    const int b0 = (gw >> 9) * 2;            // batch pair
    const int h  = gw & 511;

    const int m0   = (lane & 15) * 2;        // first of my mode pair
    const int idx0 = h * N_ + m0;
    const uint32_t uoff = (uint32_t)((lane >> 4) << 2);  // seq select in us

    const ull WR2  = pk2(d_wr[idx0],  d_wr[idx0 + 1]);
    const ull WI2  = pk2(d_wi[idx0],  d_wi[idx0 + 1]);
    const ull NWI2 = pk2(-d_wi[idx0], -d_wi[idx0 + 1]);
    const ull CSR2 = pk2(d_csr[idx0], d_csr[idx0 + 1]);
    const ull CSI2 = pk2(d_csi[idx0], d_csi[idx0 + 1]);
    const float Dh = D[h];

    const float* up0 = u + ((size_t)b0 * H_ + h) * L_;
    const float* up1 = u + ((size_t)(b0 + 1) * H_ + h) * L_;
    __half* gp0 = d_g + ((size_t)b0 * H_ + h) * L_;
    __half* gp1 = d_g + ((size_t)(b0 + 1) * H_ + h) * L_;

    ull ZR = 0ull, ZI = 0ull;

    // 2-deep u prefetch for both sequences
    float u0a = up0[lane],      u1a = up1[lane];
    float u0b = up0[32 + lane], u1b = up1[32 + lane];

    for (int l0 = 0; l0 < L_; l0 += 32) {
        us2[lane] = make_float2(u0a, u1a);
        u0a = u0b; u1a = u1b;
        if (l0 + 64 < L_) {
            u0b = up0[l0 + 64 + lane];
            u1b = up1[l0 + 64 + lane];
        }
        __syncwarp();

        #pragma unroll
        for (int t = 0; t < 32; t++) {
            float uu;
            asm volatile("ld.shared.f32 %0, [%1];"
                         : "=f"(uu) : "r"(us_a + (uint32_t)(t * 8) + uoff));
            ull UU = pk2(uu, uu);
            ull C0, C1, T0, T1;
            MUL2(C0, CSR2, UU);
            MUL2(C1, CSI2, UU);
            FMA2(T0, NWI2, ZI, C0);
            FMA2(T1, WI2,  ZR, C1);
            FMA2(ZR, WR2,  ZR, T0);
            FMA2(ZI, WR2,  ZI, T1);
            float lo, hi;
            upk2(lo, hi, ZR);
            float c = lo + hi;                 // collapse mode pair (fp32)
            asm volatile("st.shared.f32 [%0], %1;"
                         :: "r"(red_a + (uint32_t)(t * SC_RSTR + lane * 4)),
                            "f"(c) : "memory");
        }
        __syncwarp();

        // reduce: lane = timestep; read own 128B row (8 LDS.128)
        {
            const uint32_t base = red_a + (uint32_t)(lane * SC_RSTR);
            float4 v[8];
            #pragma unroll
            for (int j = 0; j < 8; j++)
                asm volatile("ld.shared.v4.f32 {%0,%1,%2,%3}, [%4];"
                             : "=f"(v[j].x), "=f"(v[j].y), "=f"(v[j].z), "=f"(v[j].w)
                             : "r"(base + (uint32_t)(j * 16)));
            // lanes 0..15 of the row = seq0 modes, 16..31 = seq1 modes
            float s0 = ((v[0].x + v[0].y) + (v[0].z + v[0].w))
                     + ((v[1].x + v[1].y) + (v[1].z + v[1].w))
                     + ((v[2].x + v[2].y) + (v[2].z + v[2].w))
                     + ((v[3].x + v[3].y) + (v[3].z + v[3].w));
            float s1 = ((v[4].x + v[4].y) + (v[4].z + v[4].w))
                     + ((v[5].x + v[5].y) + (v[5].z + v[5].w))
                     + ((v[6].x + v[6].y) + (v[6].z + v[6].w))
                     + ((v[7].x + v[7].y) + (v[7].z + v[7].w));
            float2 uvt = us2[lane];
            float y0 = fmaf(Dh, uvt.x, s0);
            float y1 = fmaf(Dh, uvt.y, s1);
            const float k = 0.70710678118654752f;
            float g0 = 0.5f * y0 * (1.0f + erff(y0 * k));
            float g1 = 0.5f * y1 * (1.0f + erff(y1 * k));
            gp0[l0 + lane] = __float2half(g0);
            gp1[l0 + lane] = __float2half(g1);
        }
        __syncwarp();
    }
}

// ---------------------------------------------------------------------------
// Kernel 3: mma.sync fp16 GEMM + GLU, single pass (proven 115us, unchanged).
// CTA: M=128 (a + gate channel halves), N=128 l-cols, BK=32, 3-stage
// cp.async pipeline, 8 warps (4M x 2N), warp tile 32x64, 2 CTAs/SM.
// ---------------------------------------------------------------------------
#define BK 32
#define SSTR 80                              // A rows: 64B + 16B pad
#define SSTRB 272                            // B rows: 256B + 16B pad
#define TILE_A 10240                         // 128 * 80
#define TILE_B (BK * SSTRB)                  // 8704
#define OFF_B  TILE_A
#define STAGEB (TILE_A + TILE_B)             // 18944
#define NSTAGE (H_ / BK)                     // 16
#define SMEM_BYTES (3 * STAGEB)              // 56832
#define BSRC_STRIDE ((size_t)BK * L_ * 2)    // 262144 bytes per stage

__global__ __launch_bounds__(256, 2) void gemm_glu_mma(const float* __restrict__ bias,
                                                       float* __restrict__ out)
{
    extern __shared__ char smem[];
    const int tid  = threadIdx.x;
    const int wid  = tid >> 5;
    const int lane = tid & 31;

    const int b  = blockIdx.x >> 5;
    const int l0 = (blockIdx.x & 31) * 128;
    const int h0 = blockIdx.y * 64;

    const uint32_t sb = smem_u32(smem);
    const int wm = wid >> 1;
    const int wn = wid & 1;

    uint32_t aoff[2], boff[4];
    {
        int rr0 = wm * 32 + (lane & 15);
        int ka  = (lane >> 4) << 4;
        aoff[0] = (uint32_t)((rr0 +  0) * SSTR + ka);
        aoff[1] = (uint32_t)((rr0 + 16) * SSTR + ka);
        int rowb = (lane & 15) * SSTRB;
        int nbase = wn * 64 + ((lane >> 4) << 3);
        #pragma unroll
        for (int jb = 0; jb < 4; jb++)
            boff[jb] = (uint32_t)(OFF_B + rowb + (nbase + jb * 16) * 2);
    }

    const char* srcs[4];
    uint32_t    dsts[4];
    #pragma unroll
    for (int j = 0; j < 2; j++) {
        int id  = tid + 256 * j;
        int row = id >> 2;
        int seg = id & 3;
        int arow = h0 + row + ((row >= 64) ? 448 : 0);
        srcs[j] = (const char*)(d_Wf + (size_t)arow * H_) + seg * 16;
        dsts[j] = sb + row * SSTR + seg * 16;
    }
    #pragma unroll
    for (int j = 2; j < 4; j++) {
        int id  = tid + 256 * (j - 2);
        int row = id >> 4;
        int seg = id & 15;
        const __half* base = d_g + (size_t)b * H_ * L_;
        srcs[j] = (const char*)(base + (size_t)row * L_ + l0) + seg * 16;
        dsts[j] = sb + OFF_B + row * SSTRB + seg * 16;
    }

    #pragma unroll
    for (int j = 0; j < 4; j++) CP_ASYNC16(dsts[j], srcs[j]);
    CP_COMMIT();
    #pragma unroll
    for (int j = 0; j < 2; j++) CP_ASYNC16(dsts[j] + STAGEB, srcs[j] + 64);
    #pragma unroll
    for (int j = 2; j < 4; j++) CP_ASYNC16(dsts[j] + STAGEB, srcs[j] + BSRC_STRIDE);
    CP_COMMIT();

    float acc[2][8][4];
    #pragma unroll
    for (int mf = 0; mf < 2; mf++)
        #pragma unroll
        for (int nf = 0; nf < 8; nf++)
            #pragma unroll
            for (int e = 0; e < 4; e++) acc[mf][nf][e] = 0.0f;

    for (int s = 0; s < NSTAGE; s++) {
        if (s == NSTAGE - 1) { CP_WAIT0(); } else { CP_WAIT1(); }
        __syncthreads();

        const uint32_t st = sb + (uint32_t)(s % 3) * STAGEB;

        #pragma unroll
        for (int ks = 0; ks < 2; ks++) {
            const uint32_t ksoA = (uint32_t)(ks * 32);
            const uint32_t ksoB = (uint32_t)(ks * 16 * SSTRB);
            uint32_t aF[2][4], bF[4][4];
            #pragma unroll
            for (int mf = 0; mf < 2; mf++)
                ldsm4(aF[mf], st + aoff[mf] + ksoA);
            #pragma unroll
            for (int jb = 0; jb < 4; jb++)
                ldsm4t(bF[jb], st + boff[jb] + ksoB);
            #pragma unroll
            for (int mf = 0; mf < 2; mf++)
                #pragma unroll
                for (int jb = 0; jb < 4; jb++)
                    #pragma unroll
                    for (int hh = 0; hh < 2; hh++)
                        mma16816(acc[mf][jb * 2 + hh], aF[mf],
                                 bF[jb][2 * hh], bF[jb][2 * hh + 1]);
        }

        if (s + 2 < NSTAGE) {
            uint32_t dbo = (uint32_t)((s + 2) % 3) * STAGEB;
            #pragma unroll
            for (int j = 0; j < 2; j++)
                CP_ASYNC16(dsts[j] + dbo, srcs[j] + (size_t)(s + 2) * 64);
            #pragma unroll
            for (int j = 2; j < 4; j++)
                CP_ASYNC16(dsts[j] + dbo, srcs[j] + (size_t)(s + 2) * BSRC_STRIDE);
            CP_COMMIT();
        }
    }
    __syncthreads();

    // ---- epilogue: GLU ----
    float* sg = (float*)smem;               // [64][130] f32
    const int r0 = (lane >> 2);
    const int c0 = (lane & 3) * 2;

    if (wm >= 2) {
        #pragma unroll
        for (int mf = 0; mf < 2; mf++) {
            int row = wm * 32 + mf * 16 + r0;     // 64..127
            int grow = row - 64;
            float bg  = bias[H_ + h0 + grow];
            float bg2 = bias[H_ + h0 + grow + 8];
            #pragma unroll
            for (int nf = 0; nf < 8; nf++) {
                int col = wn * 64 + nf * 8 + c0;
                *(float2*)&sg[grow * 130 + col] =
                    make_float2(acc[mf][nf][0] + bg, acc[mf][nf][1] + bg);
                *(float2*)&sg[(grow + 8) * 130 + col] =
                    make_float2(acc[mf][nf][2] + bg2, acc[mf][nf][3] + bg2);
            }
        }
    }
    __syncthreads();
    if (wm < 2) {
        #pragma unroll
        for (int mf = 0; mf < 2; mf++) {
            int row = wm * 32 + mf * 16 + r0;     // 0..63
            int h  = h0 + row;
            float ba  = bias[h];
            float ba2 = bias[h + 8];
            float* ob  = out + ((size_t)b * H_ + h) * L_ + l0;
            float* ob2 = out + ((size_t)b * H_ + h + 8) * L_ + l0;
            #pragma unroll
            for (int nf = 0; nf < 8; nf++) {
                int col = wn * 64 + nf * 8 + c0;
                float2 g0 = *(const float2*)&sg[row * 130 + col];
                float2 g1 = *(const float2*)&sg[(row + 8) * 130 + col];
                float2 o0, o1;
                o0.x = (acc[mf][nf][0] + ba)  / (1.0f + expf(-g0.x));
                o0.y = (acc[mf][nf][1] + ba)  / (1.0f + expf(-g0.y));
                o1.x = (acc[mf][nf][2] + ba2) / (1.0f + expf(-g1.x));
                o1.y = (acc[mf][nf][3] + ba2) / (1.0f + expf(-g1.y));
                *(float2*)(ob  + col) = o0;
                *(float2*)(ob2 + col) = o1;
            }
        }
    }
}

// ---------------------------------------------------------------------------
extern "C" void kernel_launch(void* const* d_in, const int* in_sizes, int n_in,
                              void* d_out, int out_size)
{
    const float* u          = (const float*)d_in[0];
    const float* log_dt     = (const float*)d_in[1];
    const float* log_A_real = (const float*)d_in[2];
    const float* A_imag     = (const float*)d_in[3];
    const float* C          = (const float*)d_in[4];
    const float* D          = (const float*)d_in[5];
    const float* W_out      = (const float*)d_in[6];
    const float* b_out      = (const float*)d_in[7];
    float* out = (float*)d_out;

    static bool attr_set = false;
    if (!attr_set) {
        cudaFuncSetAttribute(gemm_glu_mma, cudaFuncAttributeMaxDynamicSharedMemorySize,
                             SMEM_BYTES);
        attr_set = true;
    }

    prep_kernel<<<(HN + 127) / 128, 128>>>(log_dt, log_A_real, A_imag, C);
    wconv_kernel<<<(O_ * H_ + 255) / 256, 256>>>(W_out);

    // 2048 warps (2 sequences each, mode-pair packed), 8 warps/block
    scan_kernel<<<256, 256>>>(u, D);

    dim3 grid(B_ * (L_ / 128), H_ / 64);    // (256, 8)
    gemm_glu_mma<<<grid, 256, SMEM_BYTES>>>(b_out, out);
}